// round 13
// baseline (speedup 1.0000x reference)
#include <cuda_runtime.h>

#define N_NODES 100000
#define N_EDGES 3200000

// ---- persistent device scratch (no allocations allowed) ----
// g_deg is zero-initialized at module load; k_finish re-zeroes it every call.
__device__ int   g_deg [N_NODES];
__device__ float g_dinv[N_NODES];
__device__ float g_xn  [N_NODES * 4];   // x * dinv  (src-normalized features)
__device__ float g_agg [N_NODES * 4];   // layer-1 accumulator, init = xn (self loop)
__device__ float g_tn  [N_NODES * 2];   // t * dinv  (src-normalized layer-2 features)

// Vectorized no-return global reductions (one L2 message per 2/4 floats).
__device__ __forceinline__ void red_add_v4(float* p, float a, float b, float c, float d) {
    asm volatile("red.global.add.v4.f32 [%0], {%1,%2,%3,%4};"
                 :: "l"(p), "f"(a), "f"(b), "f"(c), "f"(d) : "memory");
}
__device__ __forceinline__ void red_add_v2(float* p, float a, float b) {
    asm volatile("red.global.add.v2.f32 [%0], {%1,%2};"
                 :: "l"(p), "f"(a), "f"(b) : "memory");
}
__device__ __forceinline__ void red_add_u32(int* p) {
    asm volatile("red.global.add.u32 [%0], 1;" :: "l"(p) : "memory");
}

// K1: degree of dst endpoints. Index stream read with __ldcs (evict-first).
__global__ void k_deg(const int* __restrict__ dst) {
    int i = blockIdx.x * blockDim.x + threadIdx.x;
    if (i < N_EDGES / 4) {
        int4 d = __ldcs(&reinterpret_cast<const int4*>(dst)[i]);
        cudaGridDependencySynchronize();
        red_add_u32(&g_deg[d.x]);
        red_add_u32(&g_deg[d.y]);
        red_add_u32(&g_deg[d.z]);
        red_add_u32(&g_deg[d.w]);
    } else {
        cudaGridDependencySynchronize();
    }
}

// K2: dinv = rsqrt(deg+1);  xn = x*dinv;  agg init = xn (layer-1 self loop).
// 2 nodes / thread: two independent chains for ILP (node kernels are
// grid-limited and latency-bound).
__global__ void k_dinv_xn(const float* __restrict__ x) {
    int i = blockIdx.x * blockDim.x + threadIdx.x;
    int v0 = 2 * i, v1 = 2 * i + 1;
    if (v0 >= N_NODES) { cudaGridDependencySynchronize(); return; }
    float4 xa = reinterpret_cast<const float4*>(x)[v0];   // independent input
    float4 xb = reinterpret_cast<const float4*>(x)[v1];
    cudaGridDependencySynchronize();                      // wait for k_deg
    int da = g_deg[v0];
    int db = g_deg[v1];
    float ia = rsqrtf((float)(da + 1));
    float ib = rsqrtf((float)(db + 1));
    g_dinv[v0] = ia;
    g_dinv[v1] = ib;
    float4 na = make_float4(xa.x * ia, xa.y * ia, xa.z * ia, xa.w * ia);
    float4 nb = make_float4(xb.x * ib, xb.y * ib, xb.z * ib, xb.w * ib);
    reinterpret_cast<float4*>(g_xn)[v0]  = na;
    reinterpret_cast<float4*>(g_xn)[v1]  = nb;
    reinterpret_cast<float4*>(g_agg)[v0] = na;
    reinterpret_cast<float4*>(g_agg)[v1] = nb;
}

// K3: layer-1 edges: agg[dst] += xn[src]  (dst factor deferred)
__global__ void k_l1_edges(const int* __restrict__ src, const int* __restrict__ dst) {
    int i = blockIdx.x * blockDim.x + threadIdx.x;
    if (i >= N_EDGES / 4) { cudaGridDependencySynchronize(); return; }
    int4 s = __ldcs(&reinterpret_cast<const int4*>(src)[i]);  // independent inputs
    int4 d = __ldcs(&reinterpret_cast<const int4*>(dst)[i]);
    cudaGridDependencySynchronize();                     // wait for k_dinv_xn
    const float4* xv = reinterpret_cast<const float4*>(g_xn);

    float4 v0 = xv[s.x];
    float4 v1 = xv[s.y];
    float4 v2 = xv[s.z];
    float4 v3 = xv[s.w];
    red_add_v4(&g_agg[4 * d.x], v0.x, v0.y, v0.z, v0.w);
    red_add_v4(&g_agg[4 * d.y], v1.x, v1.y, v1.z, v1.w);
    red_add_v4(&g_agg[4 * d.z], v2.x, v2.y, v2.z, v2.w);
    red_add_v4(&g_agg[4 * d.w], v3.x, v3.y, v3.z, v3.w);
}

// K4: per-node transform, 2 nodes / thread (two independent FMA chains).
//   a = dinv*agg; h = relu(a@W1+b1); t = h@W2; tn = t*dinv;
//   out init = tn (layer-2 self loop pre-dst-scale)
__global__ void k_xform(const float* __restrict__ W1, const float* __restrict__ b1,
                        const float* __restrict__ W2,
                        float* __restrict__ out) {
    int i = blockIdx.x * blockDim.x + threadIdx.x;
    int va = 2 * i, vb = 2 * i + 1;
    if (va >= N_NODES) { cudaGridDependencySynchronize(); return; }
    cudaGridDependencySynchronize();                     // wait for k_l1_edges
    float dia = g_dinv[va];
    float dib = g_dinv[vb];
    float4 aga = reinterpret_cast<const float4*>(g_agg)[va];
    float4 agb = reinterpret_cast<const float4*>(g_agg)[vb];
    float a0 = aga.x * dia, a1 = aga.y * dia, a2 = aga.z * dia, a3 = aga.w * dia;
    float c0 = agb.x * dib, c1 = agb.y * dib, c2 = agb.z * dib, c3 = agb.w * dib;

    float ta0 = 0.f, ta1 = 0.f, tb0 = 0.f, tb1 = 0.f;
    #pragma unroll
    for (int j = 0; j < 16; j++) {
        float w0 = W1[j], w1 = W1[16 + j], w2 = W1[32 + j], w3 = W1[48 + j];
        float bb = b1[j];
        float u0 = W2[2 * j], u1 = W2[2 * j + 1];
        float ha = fmaxf(a0 * w0 + a1 * w1 + a2 * w2 + a3 * w3 + bb, 0.f);
        float hb = fmaxf(c0 * w0 + c1 * w1 + c2 * w2 + c3 * w3 + bb, 0.f);
        ta0 += ha * u0;  ta1 += ha * u1;
        tb0 += hb * u0;  tb1 += hb * u1;
    }
    float2 na = make_float2(ta0 * dia, ta1 * dia);
    float2 nb = make_float2(tb0 * dib, tb1 * dib);
    reinterpret_cast<float2*>(g_tn)[va] = na;
    reinterpret_cast<float2*>(g_tn)[vb] = nb;
    reinterpret_cast<float2*>(out)[va]  = na;   // self-loop init
    reinterpret_cast<float2*>(out)[vb]  = nb;
}

// K5: layer-2 edges: out[dst] += tn[src]  (dst factor deferred)
__global__ void k_l2_edges(const int* __restrict__ src, const int* __restrict__ dst,
                           float* __restrict__ out) {
    int i = blockIdx.x * blockDim.x + threadIdx.x;
    if (i >= N_EDGES / 4) { cudaGridDependencySynchronize(); return; }
    int4 s = __ldcs(&reinterpret_cast<const int4*>(src)[i]);  // independent inputs
    int4 d = __ldcs(&reinterpret_cast<const int4*>(dst)[i]);
    cudaGridDependencySynchronize();                     // wait for k_xform
    const float2* tv = reinterpret_cast<const float2*>(g_tn);

    float2 t0 = tv[s.x];
    float2 t1 = tv[s.y];
    float2 t2 = tv[s.z];
    float2 t3 = tv[s.w];
    red_add_v2(&out[2 * d.x], t0.x, t0.y);
    red_add_v2(&out[2 * d.y], t1.x, t1.y);
    red_add_v2(&out[2 * d.z], t2.x, t2.y);
    red_add_v2(&out[2 * d.w], t3.x, t3.y);
}

// K6: apply deferred dst factor + bias, 2 nodes / thread.
//     Also re-zero g_deg for the next call.
__global__ void k_finish(float* __restrict__ out, const float* __restrict__ b2) {
    int i = blockIdx.x * blockDim.x + threadIdx.x;
    int va = 2 * i, vb = 2 * i + 1;
    if (va >= N_NODES) { cudaGridDependencySynchronize(); return; }
    cudaGridDependencySynchronize();                     // wait for k_l2_edges
    float c0 = b2[0], c1 = b2[1];
    float dia = g_dinv[va];
    float dib = g_dinv[vb];
    float2 oa = reinterpret_cast<float2*>(out)[va];
    float2 ob = reinterpret_cast<float2*>(out)[vb];
    reinterpret_cast<float2*>(out)[va] = make_float2(oa.x * dia + c0, oa.y * dia + c1);
    reinterpret_cast<float2*>(out)[vb] = make_float2(ob.x * dib + c0, ob.y * dib + c1);
    g_deg[va] = 0;
    g_deg[vb] = 0;
}

// PDL launch helper.
template <typename... Args>
static inline void launch_pdl(void (*kern)(Args...), int grid, int block, Args... args) {
    cudaLaunchConfig_t cfg = {};
    cfg.gridDim  = dim3(grid, 1, 1);
    cfg.blockDim = dim3(block, 1, 1);
    cudaLaunchAttribute attr[1];
    attr[0].id = cudaLaunchAttributeProgrammaticStreamSerialization;
    attr[0].val.programmaticStreamSerializationAllowed = 1;
    cfg.attrs = attr;
    cfg.numAttrs = 1;
    cudaLaunchKernelEx(&cfg, kern, args...);
}

extern "C" void kernel_launch(void* const* d_in, const int* in_sizes, int n_in,
                              void* d_out, int out_size) {
    const float* x   = (const float*)d_in[0];     // [N, 4]
    const int*   ei  = (const int*)  d_in[1];     // [2, E]
    const float* W1  = (const float*)d_in[2];     // [4, 16]
    const float* b1  = (const float*)d_in[3];     // [16]
    const float* W2  = (const float*)d_in[4];     // [16, 2]
    const float* b2  = (const float*)d_in[5];     // [2]
    float* out = (float*)d_out;                   // [N, 2]

    const int* src = ei;
    const int* dst = ei + N_EDGES;

    const int TB = 256;
    int node2Blocks = (N_NODES / 2 + TB - 1) / TB;   // 2 nodes / thread
    int edgeBlocks  = (N_EDGES / 4 + TB - 1) / TB;

    launch_pdl(k_deg,      edgeBlocks,  TB, dst);
    launch_pdl(k_dinv_xn,  node2Blocks, TB, x);
    launch_pdl(k_l1_edges, edgeBlocks,  TB, src, dst);
    launch_pdl(k_xform,    node2Blocks, TB, W1, b1, W2, out);
    launch_pdl(k_l2_edges, edgeBlocks,  TB, src, dst, out);
    launch_pdl(k_finish,   node2Blocks, TB, out, b2);
}